// round 7
// baseline (speedup 1.0000x reference)
#include <cuda_runtime.h>
#include <math.h>

// LatentRNN: B=2048, T=512, P=8, L=64, H=180
// 128 persistent CTAs x 16 batch rows, 768 threads.
// Pre-packed transposed weights (coalesced LDG.128), NC=2 fused column pairs
// in the GRU GEMM, NR=4 tasks in B/D, NR=2 in E, 6 barriers/step.

#define B_    2048
#define T_    512
#define P_    8
#define L_    64
#define H_    180
#define IN_K  72
#define BT    16
#define NTHR  768
#define GST   20          // padded row stride for giT/ghT

// packed weights: [kq][ncols] float4  (kq = k/4)
__device__ float4 g_Wc4[45 * 1080];   // fused [W_ih ; W_hh], K=180
__device__ float4 g_Wb4[18 * 180];    // W_in, K=72
__device__ float4 g_Wd4[61 * 180];    // W_o1, K=244 (kq 0-44: h part, 45-60: cur part)
__device__ float4 g_We4[45 * 64];     // W_o2, K=180
__device__ float4 g_Wh4[16 * 180];    // W_hp, K=64

#define N_C (45 * 1080)
#define N_B (18 * 180)
#define N_D (61 * 180)
#define N_E (45 * 64)
#define N_H (16 * 180)

__global__ void prep_kernel(const float* __restrict__ Wih,
                            const float* __restrict__ Whh,
                            const float* __restrict__ Win,
                            const float* __restrict__ Wo1,
                            const float* __restrict__ Wo2,
                            const float* __restrict__ Whp)
{
    int i = blockIdx.x * blockDim.x + threadIdx.x;
    if (i < N_C) {
        int kq = i / 1080, g = i - kq * 1080;
        const float* src = (g < 540) ? (Wih + g * H_ + kq * 4)
                                     : (Whh + (g - 540) * H_ + kq * 4);
        g_Wc4[kq * 1080 + g] = *(const float4*)src;
        return;
    }
    i -= N_C;
    if (i < N_B) {
        int kq = i / 180, j = i - kq * 180;
        g_Wb4[kq * 180 + j] = *(const float4*)(Win + j * IN_K + kq * 4);
        return;
    }
    i -= N_B;
    if (i < N_D) {
        int kq = i / 180, j = i - kq * 180;
        g_Wd4[kq * 180 + j] = *(const float4*)(Wo1 + j * 244 + kq * 4);
        return;
    }
    i -= N_D;
    if (i < N_E) {
        int kq = i / 64, j = i - kq * 64;
        g_We4[kq * 64 + j] = *(const float4*)(Wo2 + j * H_ + kq * 4);
        return;
    }
    i -= N_E;
    if (i < N_H) {
        int kq = i / 180, j = i - kq * 180;
        g_Wh4[kq * 180 + j] = *(const float4*)(Whp + j * L_ + kq * 4);
    }
}

struct __align__(16) Smem {
    float inT [IN_K][BT];      // [phys_t ; cur] transposed
    float xT  [H_][BT];        // gelu(in @ W_in^T)
    float hT  [2][H_][BT];     // hidden state, double buffered
    float oT  [H_][BT];        // gelu(cat @ W_o1^T)
    float giT [540][GST];      // gi (+bias); rows 0..179 overwritten with h_new
    float ghT [540][GST];      // gh (+bias)
    float catC[L_][BT];        // cur transposed (for D's K 180..243)
    float cur [BT][L_];        // current latents (row-major)
    float sb  [1684];          // ih 0 | hh 540 | in 1080 | o1 1260 | o2 1440 | hp 1504
};

__device__ __forceinline__ float gelu_f(float v) {
    return 0.5f * v * (1.0f + erff(v * 0.70710678118654752440f));
}
__device__ __forceinline__ float sigmoid_f(float v) {
    return 1.0f / (1.0f + expf(-v));
}

// NR=4 column GEMM: one column j, 4 batch rows at act+...+ro, K = 4*NKQ.
// Weight float4 at w[kq*WST]; warp-coalesced (4 lanes share one float4).
template<int NKQ, int WST, int LDA>
__device__ __forceinline__ void pcol4(const float4* __restrict__ w,
                                      const float* __restrict__ act,
                                      float* __restrict__ acc)
{
#pragma unroll 3
    for (int kq = 0; kq < NKQ; kq++) {
        float4 w4 = w[kq * WST];
        const float* b = act + kq * 4 * LDA;
        float wk[4] = {w4.x, w4.y, w4.z, w4.w};
#pragma unroll
        for (int kk = 0; kk < 4; kk++) {
            float4 a = *(const float4*)(b + kk * LDA);
            acc[0] = fmaf(a.x, wk[kk], acc[0]);
            acc[1] = fmaf(a.y, wk[kk], acc[1]);
            acc[2] = fmaf(a.z, wk[kk], acc[2]);
            acc[3] = fmaf(a.w, wk[kk], acc[3]);
        }
    }
}

__global__ __launch_bounds__(NTHR, 1)
void latent_rnn_kernel(const float* __restrict__ phys,
                       const float* __restrict__ latents,
                       const float* __restrict__ b_in,
                       const float* __restrict__ b_hp,
                       const float* __restrict__ b_ih,
                       const float* __restrict__ b_hh,
                       const float* __restrict__ b_o1,
                       const float* __restrict__ b_o2,
                       float* __restrict__ out)
{
    extern __shared__ char smem_raw[];
    Smem* s = reinterpret_cast<Smem*>(smem_raw);
    const int tid = threadIdx.x;
    const int b0  = blockIdx.x * BT;

    // ---- init ----
    for (int i = tid; i < BT * L_; i += NTHR) {
        int r = i >> 6, l = i & 63;
        float v = latents[(b0 + r) * L_ + l];
        s->cur[r][l]  = v;
        s->inT[l][r]  = v;
    }
    for (int i = tid; i < 540;  i += NTHR) s->sb[i]        = b_ih[i];
    for (int i = tid; i < 540;  i += NTHR) s->sb[540 + i]  = b_hh[i];
    for (int i = tid; i < 180;  i += NTHR) s->sb[1080 + i] = b_in[i];
    for (int i = tid; i < 180;  i += NTHR) s->sb[1260 + i] = b_o1[i];
    for (int i = tid; i < 64;   i += NTHR) s->sb[1440 + i] = b_o2[i];
    for (int i = tid; i < 180;  i += NTHR) s->sb[1504 + i] = b_hp[i];
    __syncthreads();

    // ---- h0 = latents @ W_hp^T + b_hp  (720 NR=4 tasks) ----
    if (tid < 720) {
        int j = tid >> 2, ro = (tid & 3) * 4;
        float acc[4] = {0, 0, 0, 0};
        pcol4<16, 180, BT>(g_Wh4 + j, &s->inT[0][ro], acc);
        float bb = s->sb[1504 + j];
#pragma unroll
        for (int i = 0; i < 4; i++) s->hT[0][j][ro + i] = acc[i] + bb;
    }

    for (int t = 0; t < T_; t++) {
        const int cb = t & 1, nb = cb ^ 1;
        __syncthreads();   // (0) prev-E cur / h0 ready

        // ---- A: inT = [phys_t ; cur]^T ; catC = cur^T ----
        for (int i = tid; i < BT * IN_K; i += NTHR) {
            int r = i / IN_K, k = i - r * IN_K;
            s->inT[k][r] = (k < P_) ? phys[((size_t)(b0 + r) * T_ + t) * P_ + k]
                                    : s->cur[r][k - P_];
        }
        for (int i = tid; i < L_ * BT; i += NTHR) {
            int l = i >> 4, r = i & 15;
            s->catC[l][r] = s->cur[r][l];
        }
        __syncthreads();   // (1) inT / catC ready

        // ---- B: xT = gelu(inT @ W_in^T + b_in)  (720 NR=4 tasks) ----
        if (tid < 720) {
            int j = tid >> 2, ro = (tid & 3) * 4;
            float acc[4] = {0, 0, 0, 0};
            pcol4<18, 180, BT>(g_Wb4 + j, &s->inT[0][ro], acc);
            float bb = s->sb[1080 + j];
#pragma unroll
            for (int i = 0; i < 4; i++) s->xT[j][ro + i] = gelu_f(acc[i] + bb);
        }
        __syncthreads();   // (2) xT ready

        // ---- C: gi/gh, NC=2 columns x 16 rows per thread (540 tasks) ----
        if (tid < 540) {
            const int g  = tid;
            const int j0 = 2 * g;                  // never straddles 540
            const bool ih = (j0 < 540);
            const float* act = ih ? &s->xT[0][0] : &s->hT[cb][0][0];
            const float4* w = g_Wc4 + j0;
            float acc[32];
#pragma unroll
            for (int i = 0; i < 32; i++) acc[i] = 0.f;
#pragma unroll 5
            for (int kq = 0; kq < 45; kq++) {
                float4 w0 = w[kq * 1080];
                float4 w1 = w[kq * 1080 + 1];
                const float* bp = act + kq * 4 * BT;
                float w0k[4] = {w0.x, w0.y, w0.z, w0.w};
                float w1k[4] = {w1.x, w1.y, w1.z, w1.w};
#pragma unroll
                for (int kk = 0; kk < 4; kk++) {
#pragma unroll
                    for (int rq = 0; rq < 4; rq++) {
                        float4 a = *(const float4*)(bp + kk * BT + rq * 4);
                        acc[rq*4+0]    = fmaf(a.x, w0k[kk], acc[rq*4+0]);
                        acc[rq*4+1]    = fmaf(a.y, w0k[kk], acc[rq*4+1]);
                        acc[rq*4+2]    = fmaf(a.z, w0k[kk], acc[rq*4+2]);
                        acc[rq*4+3]    = fmaf(a.w, w0k[kk], acc[rq*4+3]);
                        acc[16+rq*4+0] = fmaf(a.x, w1k[kk], acc[16+rq*4+0]);
                        acc[16+rq*4+1] = fmaf(a.y, w1k[kk], acc[16+rq*4+1]);
                        acc[16+rq*4+2] = fmaf(a.z, w1k[kk], acc[16+rq*4+2]);
                        acc[16+rq*4+3] = fmaf(a.w, w1k[kk], acc[16+rq*4+3]);
                    }
                }
            }
#pragma unroll
            for (int c = 0; c < 2; c++) {
                int col = j0 + c;
                float bb = s->sb[col];
                float* dst = ih ? s->giT[col] : s->ghT[col - 540];
#pragma unroll
                for (int rq = 0; rq < 4; rq++) {
                    float4 f;
                    f.x = acc[c*16 + rq*4+0] + bb; f.y = acc[c*16 + rq*4+1] + bb;
                    f.z = acc[c*16 + rq*4+2] + bb; f.w = acc[c*16 + rq*4+3] + bb;
                    *(float4*)(dst + rq * 4) = f;
                }
            }
        }
        __syncthreads();   // (3) gi/gh ready

        // ---- gates: h_new -> hT[nb]; giT[0..179] := h_new ----
        for (int i = tid; i < H_ * BT; i += NTHR) {
            int j = i >> 4, r = i & 15;
            float rg = sigmoid_f(s->giT[j][r]        + s->ghT[j][r]);
            float zg = sigmoid_f(s->giT[j + H_][r]   + s->ghT[j + H_][r]);
            float ng = tanhf    (s->giT[j + 2*H_][r] + rg * s->ghT[j + 2*H_][r]);
            float hn = (1.f - zg) * ng + zg * s->hT[cb][j][r];
            s->hT[nb][j][r] = hn;
            s->giT[j][r] = hn;      // owned element, read-before-write above
        }
        __syncthreads();   // (4) h_new / giT ready

        // ---- D: oT = gelu([h_new ; cur] @ W_o1^T + b_o1)  (720 NR=4 tasks) ----
        if (tid < 720) {
            int j = tid >> 2, ro = (tid & 3) * 4;
            float acc[4] = {0, 0, 0, 0};
            pcol4<45, 180, GST>(g_Wd4 + j, &s->giT[0][ro], acc);          // K 0..179
            pcol4<16, 180, BT>(g_Wd4 + 45 * 180 + j, &s->catC[0][ro], acc); // K 180..243
            float bb = s->sb[1260 + j];
#pragma unroll
            for (int i = 0; i < 4; i++) s->oT[j][ro + i] = gelu_f(acc[i] + bb);
        }
        __syncthreads();   // (5) oT ready

        // ---- E: delta = oT @ W_o2^T + b_o2; cur = clip(cur+delta); store ----
        if (tid < 512) {
            int j = tid >> 3, ro = (tid & 7) * 2;
            float a0 = 0.f, a1 = 0.f;
            const float4* w = g_We4 + j;
#pragma unroll 5
            for (int kq = 0; kq < 45; kq++) {
                float4 w4 = w[kq * 64];
                const float* bp = &s->oT[kq * 4][ro];
                float wk[4] = {w4.x, w4.y, w4.z, w4.w};
#pragma unroll
                for (int kk = 0; kk < 4; kk++) {
                    float2 a = *(const float2*)(bp + kk * BT);
                    a0 = fmaf(a.x, wk[kk], a0);
                    a1 = fmaf(a.y, wk[kk], a1);
                }
            }
            float bb = s->sb[1440 + j];
            float c0 = fminf(fmaxf(s->cur[ro][j]     + a0 + bb, 0.f), 1.f);
            float c1 = fminf(fmaxf(s->cur[ro + 1][j] + a1 + bb, 0.f), 1.f);
            s->cur[ro][j]     = c0;
            s->cur[ro + 1][j] = c1;
            out[((size_t)(b0 + ro)     * T_ + t) * L_ + j] = c0;
            out[((size_t)(b0 + ro + 1) * T_ + t) * L_ + j] = c1;
        }
    }
}

extern "C" void kernel_launch(void* const* d_in, const int* in_sizes, int n_in,
                              void* d_out, int out_size)
{
    const float* phys    = (const float*)d_in[0];
    const float* latents = (const float*)d_in[1];
    const float* W_in    = (const float*)d_in[2];
    const float* b_in    = (const float*)d_in[3];
    const float* W_hp    = (const float*)d_in[4];
    const float* b_hp    = (const float*)d_in[5];
    const float* W_ih    = (const float*)d_in[6];
    const float* b_ih    = (const float*)d_in[7];
    const float* W_hh    = (const float*)d_in[8];
    const float* b_hh    = (const float*)d_in[9];
    const float* W_o1    = (const float*)d_in[10];
    const float* b_o1    = (const float*)d_in[11];
    const float* W_o2    = (const float*)d_in[12];
    const float* b_o2    = (const float*)d_in[13];
    float* out = (float*)d_out;

    static bool attr_set = false;
    if (!attr_set) {
        cudaFuncSetAttribute(latent_rnn_kernel,
                             cudaFuncAttributeMaxDynamicSharedMemorySize,
                             (int)sizeof(Smem));
        attr_set = true;
    }

    prep_kernel<<<(N_C + N_B + N_D + N_E + N_H + 255) / 256, 256>>>(
        W_ih, W_hh, W_in, W_o1, W_o2, W_hp);

    latent_rnn_kernel<<<B_ / BT, NTHR, sizeof(Smem)>>>(
        phys, latents, b_in, b_hp, b_ih, b_hh, b_o1, b_o2, out);
}